// round 14
// baseline (speedup 1.0000x reference)
#include <cuda_runtime.h>
#include <math.h>
#include <stdint.h>

// ---------------------------------------------------------------------------
// AdaptivePatchEmbedding — B=128,C=32,S=336 -> N=4096, R=7, TARGET=6, D=512
// Straight-through gumbel == one-hot: compute only selected expert per region.
// Unique patch rows per region: P=8 ->6, P=16/24 ->2, P=48 ->1.
// TWO launches: router (pe table + expert compaction) -> persistent fused
// embed: block-synchronous per-expert phases, smem-staged W (P<=24),
// STATIC chunk assignment (offset-rotated remainders), and cp.async
// double-buffered xrs fill hidden under compute. 1 barrier per chunk,
// no hot-path atomics.
// ---------------------------------------------------------------------------

#define NREG 28672            // 4096 * 7
#define XP_ELEMS 88080384LL   // 4096 * 42 * 512

__device__ int   g_counts[4];   // zero at module load; embed resets at end
__device__ int   g_done;
__device__ int   g_lists[4 * NREG];
__device__ float g_pe[42 * 512];

#define CP_ASYNC16(dst, src) \
    asm volatile("cp.async.cg.shared.global [%0], [%1], 16;" \
                 :: "r"(dst), "l"(src))
#define CP_COMMIT() asm volatile("cp.async.commit_group;" ::: "memory")
#define CP_WAIT0()  asm volatile("cp.async.wait_group 0;" ::: "memory")

// --------------------------- stage 1: router + pe table ---------------------
__global__ void __launch_bounds__(64) router_kernel(
    const float* __restrict__ x,  const float* __restrict__ un,
    const float* __restrict__ W1, const float* __restrict__ b1,
    const float* __restrict__ W2, const float* __restrict__ b2,
    float* __restrict__ out, int write_mode)
{
    __shared__ float W1s[48 * 64];
    __shared__ float W2s[256];
    __shared__ float b1s[64];
    int tid = threadIdx.x;
    int region = blockIdx.x * 64 + tid;      // grid = 448 -> exactly 28672

    // pe table: one dim-pair per thread, first 10752 threads; fp64 exp
    // latency hides under the MLP below.
    if (region < 10752) {
        int pos = region >> 8;               // [0,42)
        int tp  = region & 255;              // dim pair [0,256)
        double dv = exp((double)(2 * tp) * -(log(10000.0) / 512.0));
        float ang = (float)((double)pos * dv);
        float2 sc = make_float2(sinf(ang), cosf(ang));
        *(float2*)&g_pe[pos * 512 + 2 * tp] = sc;
    }

    for (int i = tid; i < 768; i += 64) ((float4*)W1s)[i] = ((const float4*)W1)[i];
    ((float4*)W2s)[tid] = ((const float4*)W2)[tid];
    b1s[tid] = b1[tid];
    __syncthreads();

    int n = region / 7, r = region - n * 7;

    float xr[48];
    const float4* xp = (const float4*)x + n * 84 + r * 12;
#pragma unroll
    for (int v = 0; v < 12; v++) {
        float4 t4 = xp[v];
        xr[4*v+0] = t4.x; xr[4*v+1] = t4.y; xr[4*v+2] = t4.z; xr[4*v+3] = t4.w;
    }

    float lg0 = b2[0], lg1 = b2[1], lg2 = b2[2], lg3 = b2[3];
#pragma unroll 2
    for (int k = 0; k < 64; k++) {
        float s = b1s[k];
#pragma unroll
        for (int j = 0; j < 48; j++) s = fmaf(xr[j], W1s[j * 64 + k], s);
        s = fmaxf(s, 0.0f);
        lg0 = fmaf(s, W2s[k*4+0], lg0);
        lg1 = fmaf(s, W2s[k*4+1], lg1);
        lg2 = fmaf(s, W2s[k*4+2], lg2);
        lg3 = fmaf(s, W2s[k*4+3], lg3);
    }

    const float* up = un + (long long)region * 4;
    float z0 = lg0 - logf(-logf(up[0] + 1e-10f) + 1e-10f);
    float z1 = lg1 - logf(-logf(up[1] + 1e-10f) + 1e-10f);
    float z2 = lg2 - logf(-logf(up[2] + 1e-10f) + 1e-10f);
    float z3 = lg3 - logf(-logf(up[3] + 1e-10f) + 1e-10f);

    int e = 0; float best = z0;              // first-max semantics like jnp.argmax
    if (z1 > best) { best = z1; e = 1; }
    if (z2 > best) { best = z2; e = 2; }
    if (z3 > best) { best = z3; e = 3; }

    int slot = atomicAdd(&g_counts[e], 1);
    g_lists[e * NREG + slot] = region;

    if (write_mode >= 2) out[XP_ELEMS + 1 + (long long)r * 4096 + n] = (float)e;
    if (write_mode >= 1 && region == 0) out[XP_ELEMS] = 32.0f;
}

// --------------------------- stage 2: persistent fused embed ----------------
// Chunk = 12 unique rows (RPB regions) x 512 cols; thread (tx in [0,128),
// ty in {0,1}) owns 6 rows x 4 cols. K = 7-48/P repeats, U = ceil(6/K),
// RPB = 12/U. Block b statically takes chunks ((b-off) mod grid) + k*grid.

template<int P, int E>
__device__ __forceinline__ void fill_async(
    int base, int cnt, const float4* __restrict__ x4, uint32_t dst)
{
    constexpr int K   = 7 - 48 / P;
    constexpr int U   = (6 + K - 1) / K;
    constexpr int RPB = 12 / U;
    const int nval = min(RPB, cnt - base);
    for (int i = threadIdx.x; i < nval * 12; i += 256) {
        int reg = i / 12, v = i - reg * 12;
        int rid = __ldg(&g_lists[E * NREG + base + reg]);
        int n = rid / 7, r = rid - n * 7;
        CP_ASYNC16(dst + (unsigned)i * 16u,
                   (const void*)(x4 + n * 84 + r * 12 + v));
    }
}

template<int P, int E, bool WSM>
__device__ __forceinline__ void compute_chunk(
    int base, int cnt,
    const float4* __restrict__ W4, float4* __restrict__ out4,
    const float* Wsm, const float* xrs)
{
    constexpr int K   = 7 - 48 / P;
    constexpr int U   = (6 + K - 1) / K;
    constexpr int RPB = 12 / U;

    const int tid = threadIdx.x;
    const int tx  = tid & 127, ty = tid >> 7;
    const int nval = min(RPB, cnt - base);
    const int* lst = g_lists + E * NREG + base;

    int aoff[6];
#pragma unroll
    for (int rr = 0; rr < 6; rr++) {
        int row = ty * 6 + rr;
        aoff[rr] = (row / U) * 48 + (row % U) * P;   // multiple of 4 floats
    }

    float4 acc[6];
#pragma unroll
    for (int i = 0; i < 6; i++) acc[i] = make_float4(0.f, 0.f, 0.f, 0.f);

#pragma unroll
    for (int k = 0; k < P; k += 4) {
        float4 b0 = WSM ? ((const float4*)Wsm)[(k + 0) * 128 + tx]
                        : __ldg(&W4[(k + 0) * 128 + tx]);
        float4 b1 = WSM ? ((const float4*)Wsm)[(k + 1) * 128 + tx]
                        : __ldg(&W4[(k + 1) * 128 + tx]);
        float4 b2 = WSM ? ((const float4*)Wsm)[(k + 2) * 128 + tx]
                        : __ldg(&W4[(k + 2) * 128 + tx]);
        float4 b3 = WSM ? ((const float4*)Wsm)[(k + 3) * 128 + tx]
                        : __ldg(&W4[(k + 3) * 128 + tx]);
#pragma unroll
        for (int rr = 0; rr < 6; rr++) {
            float4 a = *(const float4*)&xrs[aoff[rr] + k];   // 1 LDS.128
            acc[rr].x = fmaf(a.x, b0.x, acc[rr].x);
            acc[rr].y = fmaf(a.x, b0.y, acc[rr].y);
            acc[rr].z = fmaf(a.x, b0.z, acc[rr].z);
            acc[rr].w = fmaf(a.x, b0.w, acc[rr].w);
            acc[rr].x = fmaf(a.y, b1.x, acc[rr].x);
            acc[rr].y = fmaf(a.y, b1.y, acc[rr].y);
            acc[rr].z = fmaf(a.y, b1.z, acc[rr].z);
            acc[rr].w = fmaf(a.y, b1.w, acc[rr].w);
            acc[rr].x = fmaf(a.z, b2.x, acc[rr].x);
            acc[rr].y = fmaf(a.z, b2.y, acc[rr].y);
            acc[rr].z = fmaf(a.z, b2.z, acc[rr].z);
            acc[rr].w = fmaf(a.z, b2.w, acc[rr].w);
            acc[rr].x = fmaf(a.w, b3.x, acc[rr].x);
            acc[rr].y = fmaf(a.w, b3.y, acc[rr].y);
            acc[rr].z = fmaf(a.w, b3.z, acc[rr].z);
            acc[rr].w = fmaf(a.w, b3.w, acc[rr].w);
        }
    }

    const float4* pe4 = (const float4*)g_pe;
#pragma unroll
    for (int rr = 0; rr < 6; rr++) {
        int row = ty * 6 + rr;
        int reg = row / U;
        int q   = row % U;
        if (reg >= nval) continue;
        int rid = __ldg(&lst[reg]);
        int n = rid / 7, r = rid - n * 7;
#pragma unroll
        for (int t = q * K; t < ((q + 1) * K < 6 ? (q + 1) * K : 6); t++) {
            int pos = r * 6 + t;
            float4 p = __ldg(&pe4[pos * 128 + tx]);
            float4 v = make_float4(acc[rr].x + p.x, acc[rr].y + p.y,
                                   acc[rr].z + p.z, acc[rr].w + p.w);
            __stcs(&out4[(long long)n * 5376 + pos * 128 + tx], v);
        }
    }
}

template<int P, bool WSM>
__device__ __forceinline__ void embed_expert(
    const float4* __restrict__ x4, const float4* __restrict__ W4,
    float4* __restrict__ out4, float* Wsm, float* xrs2, uint32_t xrs2_u32,
    int boff)
{
    constexpr int E   = (P == 8) ? 0 : (P == 16) ? 1 : (P == 24) ? 2 : 3;
    constexpr int K   = 7 - 48 / P;
    constexpr int U   = (6 + K - 1) / K;
    constexpr int RPB = 12 / U;

    const int cnt = g_counts[E];
    const int nch = (cnt + RPB - 1) / RPB;
    const int gsz = gridDim.x;

    if (WSM) {
        for (int i = threadIdx.x; i < P * 128; i += 256)
            ((float4*)Wsm)[i] = W4[i];
    }

    int b0 = (int)blockIdx.x - boff; if (b0 < 0) b0 += gsz;
    int c = b0;

    if (c < nch) fill_async<P, E>(c * RPB, cnt, x4, xrs2_u32);
    CP_COMMIT(); CP_WAIT0();
    __syncthreads();                          // fill(c0) + W staging visible

    int buf = 0;
    while (c < nch) {
        int cn = c + gsz;
        if (cn < nch) {
            fill_async<P, E>(cn * RPB, cnt, x4,
                             xrs2_u32 + (unsigned)((buf ^ 1) * 576 * 4));
            CP_COMMIT();
        }
        compute_chunk<P, E, WSM>(c * RPB, cnt, W4, out4, Wsm,
                                 xrs2 + buf * 576);
        CP_WAIT0();                           // next fill done (hidden by compute)
        __syncthreads();
        buf ^= 1; c = cn;
    }
    __syncthreads();                          // phase separation (block-local)
}

__global__ void __launch_bounds__(256, 4) embed_fused_kernel(
    const float4* __restrict__ x4,
    const float4* __restrict__ We0, const float4* __restrict__ We1,
    const float4* __restrict__ We2, const float4* __restrict__ We3,
    float4* __restrict__ out4)
{
    extern __shared__ float sm[];
    float* Wsm  = sm;                      // up to 24*512 floats
    float* xrs2 = sm + 24 * 512;           // 2 * 576 floats (double buffer)

    uint32_t xrs2_u32;
    asm("{ .reg .u64 t; cvta.to.shared.u64 t, %1; cvt.u32.u64 %0, t; }"
        : "=r"(xrs2_u32) : "l"(xrs2));

    // static remainder rotation: offset each phase by cumulative chunk count
    const int gsz = gridDim.x;
    int nch3 = (g_counts[3] + 11) / 12;
    int nch2 = (g_counts[2] + 5) / 6;
    int nch1 = (g_counts[1] + 5) / 6;
    int off3 = 0;
    int off2 = nch3 % gsz;
    int off1 = (nch3 + nch2) % gsz;
    int off0 = (nch3 + nch2 + nch1) % gsz;

    embed_expert<48, false>(x4, We3, out4, Wsm, xrs2, xrs2_u32, off3);
    embed_expert<24, true >(x4, We2, out4, Wsm, xrs2, xrs2_u32, off2);
    embed_expert<16, true >(x4, We1, out4, Wsm, xrs2, xrs2_u32, off1);
    embed_expert< 8, true >(x4, We0, out4, Wsm, xrs2, xrs2_u32, off0);

    // last block out resets routing state for the next graph replay
    if (threadIdx.x == 0) {
        int d = atomicAdd(&g_done, 1);
        if (d == (int)gridDim.x - 1) {
            g_counts[0] = 0; g_counts[1] = 0; g_counts[2] = 0; g_counts[3] = 0;
            g_done = 0;
        }
    }
}

// --------------------------- launch ------------------------------------------
extern "C" void kernel_launch(void* const* d_in, const int* in_sizes, int n_in,
                              void* d_out, int out_size) {
    const float* x  = (const float*)d_in[0];
    const float* un = (const float*)d_in[1];
    const float* W1 = (const float*)d_in[2];
    const float* b1 = (const float*)d_in[3];
    const float* W2 = (const float*)d_in[4];
    const float* b2 = (const float*)d_in[5];
    const float4* We0 = (const float4*)d_in[6];
    const float4* We1 = (const float4*)d_in[7];
    const float4* We2 = (const float4*)d_in[8];
    const float4* We3 = (const float4*)d_in[9];
    float*  out  = (float*)d_out;
    float4* out4 = (float4*)d_out;
    const float4* x4 = (const float4*)d_in[0];

    int write_mode = 0;
    if ((long long)out_size >= XP_ELEMS + 1 + 28672) write_mode = 2;
    else if ((long long)out_size >= XP_ELEMS + 1)    write_mode = 1;

    const int SMEM = (24 * 512 + 2 * 576) * 4;   // 53760 bytes
    cudaFuncSetAttribute(embed_fused_kernel,
                         cudaFuncAttributeMaxDynamicSharedMemorySize, SMEM);

    router_kernel<<<448, 64>>>(x, un, W1, b1, W2, b2, out, write_mode);
    embed_fused_kernel<<<592, 256, SMEM>>>(x4, We0, We1, We2, We3, out4);
    (void)in_sizes; (void)n_in;
}

// round 15
// speedup vs baseline: 1.0029x; 1.0029x over previous
#include <cuda_runtime.h>
#include <math.h>
#include <stdint.h>

// ---------------------------------------------------------------------------
// AdaptivePatchEmbedding — B=128,C=32,S=336 -> N=4096, R=7, TARGET=6, D=512
// Straight-through gumbel == one-hot: compute only selected expert per region.
// Unique patch rows per region: P=8 ->6, P=16/24 ->2, P=48 ->1.
// TWO launches: router (pe table + compaction into 28 (expert,r) BUCKETS) ->
// persistent fused embed. Chunks are drawn from one (e,r) bucket so every
// region in a chunk shares r: the epilogue hoists the positional-embedding
// load out of the row loop (1 pe LDG per t instead of per store), cutting
// pe L1 traffic ~4-6x. Mainloop/W-staging/cursors identical to the proven
// 91.6us configuration.
// ---------------------------------------------------------------------------

#define NB 28                 // 4 experts x 7 region slots
#define XP_ELEMS 88080384LL   // 4096 * 42 * 512

__device__ int   g_cnt[NB];     // zero at module load; embed resets at end
__device__ int   g_cur[NB];
__device__ int   g_done;
__device__ int   g_lists[NB * 4096];   // bucket entries = sequence index n
__device__ float g_pe[42 * 512];

// --------------------------- stage 1: router + pe table ---------------------
__global__ void __launch_bounds__(64) router_kernel(
    const float* __restrict__ x,  const float* __restrict__ un,
    const float* __restrict__ W1, const float* __restrict__ b1,
    const float* __restrict__ W2, const float* __restrict__ b2,
    float* __restrict__ out, int write_mode)
{
    __shared__ float W1s[48 * 64];
    __shared__ float W2s[256];
    __shared__ float b1s[64];
    int tid = threadIdx.x;
    int region = blockIdx.x * 64 + tid;      // grid = 448 -> exactly 28672

    // pe table: one dim-pair per thread, first 10752 threads; fp64 exp
    // latency hides under the MLP below.
    if (region < 10752) {
        int pos = region >> 8;               // [0,42)
        int tp  = region & 255;              // dim pair [0,256)
        double dv = exp((double)(2 * tp) * -(log(10000.0) / 512.0));
        float ang = (float)((double)pos * dv);
        float2 sc = make_float2(sinf(ang), cosf(ang));
        *(float2*)&g_pe[pos * 512 + 2 * tp] = sc;
    }

    for (int i = tid; i < 768; i += 64) ((float4*)W1s)[i] = ((const float4*)W1)[i];
    ((float4*)W2s)[tid] = ((const float4*)W2)[tid];
    b1s[tid] = b1[tid];
    __syncthreads();

    int n = region / 7, r = region - n * 7;

    float xr[48];
    const float4* xp = (const float4*)x + n * 84 + r * 12;
#pragma unroll
    for (int v = 0; v < 12; v++) {
        float4 t4 = xp[v];
        xr[4*v+0] = t4.x; xr[4*v+1] = t4.y; xr[4*v+2] = t4.z; xr[4*v+3] = t4.w;
    }

    float lg0 = b2[0], lg1 = b2[1], lg2 = b2[2], lg3 = b2[3];
#pragma unroll 2
    for (int k = 0; k < 64; k++) {
        float s = b1s[k];
#pragma unroll
        for (int j = 0; j < 48; j++) s = fmaf(xr[j], W1s[j * 64 + k], s);
        s = fmaxf(s, 0.0f);
        lg0 = fmaf(s, W2s[k*4+0], lg0);
        lg1 = fmaf(s, W2s[k*4+1], lg1);
        lg2 = fmaf(s, W2s[k*4+2], lg2);
        lg3 = fmaf(s, W2s[k*4+3], lg3);
    }

    const float* up = un + (long long)region * 4;
    float z0 = lg0 - logf(-logf(up[0] + 1e-10f) + 1e-10f);
    float z1 = lg1 - logf(-logf(up[1] + 1e-10f) + 1e-10f);
    float z2 = lg2 - logf(-logf(up[2] + 1e-10f) + 1e-10f);
    float z3 = lg3 - logf(-logf(up[3] + 1e-10f) + 1e-10f);

    int e = 0; float best = z0;              // first-max semantics like jnp.argmax
    if (z1 > best) { best = z1; e = 1; }
    if (z2 > best) { best = z2; e = 2; }
    if (z3 > best) { best = z3; e = 3; }

    int bidx = e * 7 + r;
    int slot = atomicAdd(&g_cnt[bidx], 1);
    g_lists[bidx * 4096 + slot] = n;

    if (write_mode >= 2) out[XP_ELEMS + 1 + (long long)r * 4096 + n] = (float)e;
    if (write_mode >= 1 && region == 0) out[XP_ELEMS] = 32.0f;
}

// --------------------------- stage 2: persistent fused embed ----------------
// Chunk = 12 unique rows (RPB regions) x 512 cols, all regions sharing r.
// Thread (tx in [0,128), ty in {0,1}) owns 6 rows x 4 cols.
// K = 7-48/P repeats, U = ceil(6/K), RPB = 12/U, RL = 6/U regions per ty.
// Epilogue: t-outer, one pe load per t reused across rows.
template<int P, bool WSM>
__device__ __forceinline__ void embed_expert(
    const float4* __restrict__ x4, const float4* __restrict__ W4,
    float4* __restrict__ out4, float* Wsm, float* xrs, int* ibuf)
{
    constexpr int E   = (P == 8) ? 0 : (P == 16) ? 1 : (P == 24) ? 2 : 3;
    constexpr int K   = 7 - 48 / P;
    constexpr int U   = (6 + K - 1) / K;
    constexpr int RPB = 12 / U;
    constexpr int RL  = 6 / U;

    const int tid = threadIdx.x;

    if (WSM) {
        for (int i = tid; i < P * 128; i += 256)
            ((float4*)Wsm)[i] = W4[i];
    }
    const int tx = tid & 127, ty = tid >> 7;

    int aoff[6];
#pragma unroll
    for (int rr = 0; rr < 6; rr++) {
        int row = ty * 6 + rr;
        aoff[rr] = (row / U) * 48 + (row % U) * P;   // multiple of 4 floats
    }

    for (int r = 0; r < 7; r++) {
        const int bidx = E * 7 + r;
        const int cnt  = g_cnt[bidx];
        const int* lst = g_lists + bidx * 4096;

        for (;;) {
            if (tid == 0) ibuf[15] = atomicAdd(&g_cur[bidx], 1);
            __syncthreads();
            int base = ibuf[15] * RPB;
            if (base >= cnt) break;
            int nval = min(RPB, cnt - base);
            if (tid < nval) ibuf[tid] = lst[base + tid];
            __syncthreads();

            for (int i = tid; i < nval * 12; i += 256) {
                int reg = i / 12, v = i - reg * 12;
                int n = ibuf[reg];
                ((float4*)xrs)[reg * 12 + v] = __ldg(&x4[n * 84 + r * 12 + v]);
            }
            __syncthreads();

            float4 acc[6];
#pragma unroll
            for (int i = 0; i < 6; i++) acc[i] = make_float4(0.f, 0.f, 0.f, 0.f);

#pragma unroll
            for (int k = 0; k < P; k += 4) {
                float4 b0 = WSM ? ((const float4*)Wsm)[(k + 0) * 128 + tx]
                                : __ldg(&W4[(k + 0) * 128 + tx]);
                float4 b1 = WSM ? ((const float4*)Wsm)[(k + 1) * 128 + tx]
                                : __ldg(&W4[(k + 1) * 128 + tx]);
                float4 b2 = WSM ? ((const float4*)Wsm)[(k + 2) * 128 + tx]
                                : __ldg(&W4[(k + 2) * 128 + tx]);
                float4 b3 = WSM ? ((const float4*)Wsm)[(k + 3) * 128 + tx]
                                : __ldg(&W4[(k + 3) * 128 + tx]);
#pragma unroll
                for (int rr = 0; rr < 6; rr++) {
                    float4 a = *(const float4*)&xrs[aoff[rr] + k]; // 1 LDS.128
                    acc[rr].x = fmaf(a.x, b0.x, acc[rr].x);
                    acc[rr].y = fmaf(a.x, b0.y, acc[rr].y);
                    acc[rr].z = fmaf(a.x, b0.z, acc[rr].z);
                    acc[rr].w = fmaf(a.x, b0.w, acc[rr].w);
                    acc[rr].x = fmaf(a.y, b1.x, acc[rr].x);
                    acc[rr].y = fmaf(a.y, b1.y, acc[rr].y);
                    acc[rr].z = fmaf(a.y, b1.z, acc[rr].z);
                    acc[rr].w = fmaf(a.y, b1.w, acc[rr].w);
                    acc[rr].x = fmaf(a.z, b2.x, acc[rr].x);
                    acc[rr].y = fmaf(a.z, b2.y, acc[rr].y);
                    acc[rr].z = fmaf(a.z, b2.z, acc[rr].z);
                    acc[rr].w = fmaf(a.z, b2.w, acc[rr].w);
                    acc[rr].x = fmaf(a.w, b3.x, acc[rr].x);
                    acc[rr].y = fmaf(a.w, b3.y, acc[rr].y);
                    acc[rr].z = fmaf(a.w, b3.z, acc[rr].z);
                    acc[rr].w = fmaf(a.w, b3.w, acc[rr].w);
                }
            }

            // epilogue: t-outer, pe loaded ONCE per t (shared r!)
            const float4* pe4 = (const float4*)g_pe;
#pragma unroll
            for (int t = 0; t < 6; t++) {
                const int q   = t / K;                    // compile-time
                const int pos = r * 6 + t;
                float4 p = __ldg(&pe4[pos * 128 + tx]);
#pragma unroll
                for (int rl = 0; rl < RL; rl++) {
                    int rr  = rl * U + q;                 // acc row
                    int reg = ty * RL + rl;               // region in chunk
                    if (reg >= nval) continue;
                    int n = ibuf[reg];
                    float4 v = make_float4(acc[rr].x + p.x, acc[rr].y + p.y,
                                           acc[rr].z + p.z, acc[rr].w + p.w);
                    __stcs(&out4[(long long)n * 5376 + pos * 128 + tx], v);
                }
            }
            __syncthreads();
        }
    }
    __syncthreads();   // all threads done with ibuf before next expert reuses it
}

__global__ void __launch_bounds__(256, 4) embed_fused_kernel(
    const float4* __restrict__ x4,
    const float4* __restrict__ We0, const float4* __restrict__ We1,
    const float4* __restrict__ We2, const float4* __restrict__ We3,
    float4* __restrict__ out4)
{
    extern __shared__ float sm[];
    float* Wsm = sm;                       // up to 24*512 floats
    float* xrs = sm + 24 * 512;            // 12*48 floats
    int*   ibuf = (int*)(xrs + 12 * 48);   // 16 ints

    embed_expert<48, false>(x4, We3, out4, Wsm, xrs, ibuf);
    embed_expert<24, true >(x4, We2, out4, Wsm, xrs, ibuf);
    embed_expert<16, true >(x4, We1, out4, Wsm, xrs, ibuf);
    embed_expert< 8, true >(x4, We0, out4, Wsm, xrs, ibuf);

    // last block out resets routing state for the next graph replay
    if (threadIdx.x == 0) {
        int d = atomicAdd(&g_done, 1);
        if (d == (int)gridDim.x - 1) {
#pragma unroll
            for (int i = 0; i < NB; i++) { g_cnt[i] = 0; g_cur[i] = 0; }
            g_done = 0;
        }
    }
}

// --------------------------- launch ------------------------------------------
extern "C" void kernel_launch(void* const* d_in, const int* in_sizes, int n_in,
                              void* d_out, int out_size) {
    const float* x  = (const float*)d_in[0];
    const float* un = (const float*)d_in[1];
    const float* W1 = (const float*)d_in[2];
    const float* b1 = (const float*)d_in[3];
    const float* W2 = (const float*)d_in[4];
    const float* b2 = (const float*)d_in[5];
    const float4* We0 = (const float4*)d_in[6];
    const float4* We1 = (const float4*)d_in[7];
    const float4* We2 = (const float4*)d_in[8];
    const float4* We3 = (const float4*)d_in[9];
    float*  out  = (float*)d_out;
    float4* out4 = (float4*)d_out;
    const float4* x4 = (const float4*)d_in[0];

    int write_mode = 0;
    if ((long long)out_size >= XP_ELEMS + 1 + 28672) write_mode = 2;
    else if ((long long)out_size >= XP_ELEMS + 1)    write_mode = 1;

    const int SMEM = (24 * 512 + 12 * 48) * 4 + 64;   // 51520 bytes
    cudaFuncSetAttribute(embed_fused_kernel,
                         cudaFuncAttributeMaxDynamicSharedMemorySize, SMEM);

    router_kernel<<<448, 64>>>(x, un, W1, b1, W2, b2, out, write_mode);
    embed_fused_kernel<<<592, 256, SMEM>>>(x4, We0, We1, We2, We3, out4);
    (void)in_sizes; (void)n_in;
}

// round 16
// speedup vs baseline: 1.0923x; 1.0892x over previous
#include <cuda_runtime.h>
#include <math.h>
#include <stdint.h>

// ---------------------------------------------------------------------------
// AdaptivePatchEmbedding — B=128,C=32,S=336 -> N=4096, R=7, TARGET=6, D=512
// Straight-through gumbel == one-hot: compute only selected expert per region.
// Unique patch rows per region: P=8 ->6, P=16/24 ->2, P=48 ->1.
// TWO launches: router (pe table + expert compaction) -> persistent fused
// embed (R12 machinery) with SUPER-CHUNKS: one cursor grab = 24 unique rows,
// computed as two 12-row halves sharing one fill; end-of-loop barrier elided
// (post-atomic barrier provides the ordering). 1 barrier per old-chunk.
// ---------------------------------------------------------------------------

#define NREG 28672            // 4096 * 7
#define XP_ELEMS 88080384LL   // 4096 * 42 * 512

__device__ int   g_counts[4];   // zero at module load; embed resets at end
__device__ int   g_cursor[4];
__device__ int   g_done;
__device__ int   g_lists[4 * NREG];
__device__ float g_pe[42 * 512];

// --------------------------- stage 1: router + pe table ---------------------
__global__ void __launch_bounds__(64) router_kernel(
    const float* __restrict__ x,  const float* __restrict__ un,
    const float* __restrict__ W1, const float* __restrict__ b1,
    const float* __restrict__ W2, const float* __restrict__ b2,
    float* __restrict__ out, int write_mode)
{
    __shared__ float W1s[48 * 64];
    __shared__ float W2s[256];
    __shared__ float b1s[64];
    int tid = threadIdx.x;
    int region = blockIdx.x * 64 + tid;      // grid = 448 -> exactly 28672

    // pe table: one dim-pair per thread, first 10752 threads; fp64 exp
    // latency hides under the MLP below.
    if (region < 10752) {
        int pos = region >> 8;               // [0,42)
        int tp  = region & 255;              // dim pair [0,256)
        double dv = exp((double)(2 * tp) * -(log(10000.0) / 512.0));
        float ang = (float)((double)pos * dv);
        float2 sc = make_float2(sinf(ang), cosf(ang));
        *(float2*)&g_pe[pos * 512 + 2 * tp] = sc;
    }

    for (int i = tid; i < 768; i += 64) ((float4*)W1s)[i] = ((const float4*)W1)[i];
    ((float4*)W2s)[tid] = ((const float4*)W2)[tid];
    b1s[tid] = b1[tid];
    __syncthreads();

    int n = region / 7, r = region - n * 7;

    float xr[48];
    const float4* xp = (const float4*)x + n * 84 + r * 12;
#pragma unroll
    for (int v = 0; v < 12; v++) {
        float4 t4 = xp[v];
        xr[4*v+0] = t4.x; xr[4*v+1] = t4.y; xr[4*v+2] = t4.z; xr[4*v+3] = t4.w;
    }

    float lg0 = b2[0], lg1 = b2[1], lg2 = b2[2], lg3 = b2[3];
#pragma unroll 2
    for (int k = 0; k < 64; k++) {
        float s = b1s[k];
#pragma unroll
        for (int j = 0; j < 48; j++) s = fmaf(xr[j], W1s[j * 64 + k], s);
        s = fmaxf(s, 0.0f);
        lg0 = fmaf(s, W2s[k*4+0], lg0);
        lg1 = fmaf(s, W2s[k*4+1], lg1);
        lg2 = fmaf(s, W2s[k*4+2], lg2);
        lg3 = fmaf(s, W2s[k*4+3], lg3);
    }

    const float* up = un + (long long)region * 4;
    float z0 = lg0 - logf(-logf(up[0] + 1e-10f) + 1e-10f);
    float z1 = lg1 - logf(-logf(up[1] + 1e-10f) + 1e-10f);
    float z2 = lg2 - logf(-logf(up[2] + 1e-10f) + 1e-10f);
    float z3 = lg3 - logf(-logf(up[3] + 1e-10f) + 1e-10f);

    int e = 0; float best = z0;              // first-max semantics like jnp.argmax
    if (z1 > best) { best = z1; e = 1; }
    if (z2 > best) { best = z2; e = 2; }
    if (z3 > best) { best = z3; e = 3; }

    int slot = atomicAdd(&g_counts[e], 1);
    g_lists[e * NREG + slot] = region;

    if (write_mode >= 2) out[XP_ELEMS + 1 + (long long)r * 4096 + n] = (float)e;
    if (write_mode >= 1 && region == 0) out[XP_ELEMS] = 32.0f;
}

// --------------------------- stage 2: persistent fused embed ----------------
// SUPER-CHUNK = 24 unique rows (RPB2 regions); computed as 2 halves of
// 12 rows. Thread (tx in [0,128), ty in {0,1}) owns 6 rows x 4 cols per half.
// K = 7-48/P, U = ceil(6/K), RPB2 = 24/U, RH = 12/U regions per half.
template<int P, bool WSM>
__device__ __forceinline__ void embed_expert(
    const float4* __restrict__ x4, const float4* __restrict__ W4,
    float4* __restrict__ out4, float* Wsm, float* xrs, int* ibuf)
{
    constexpr int E    = (P == 8) ? 0 : (P == 16) ? 1 : (P == 24) ? 2 : 3;
    constexpr int K    = 7 - 48 / P;
    constexpr int U    = (6 + K - 1) / K;
    constexpr int RPB2 = 24 / U;       // regions per super-chunk
    constexpr int RH   = 12 / U;       // regions per half
    constexpr int HOFF = RH * 48;      // xrs float offset of half 1

    const int tid = threadIdx.x;
    const int cnt = g_counts[E];

    if (WSM) {
        for (int i = tid; i < P * 128; i += 256)
            ((float4*)Wsm)[i] = W4[i];
    }
    const int tx = tid & 127, ty = tid >> 7;

    int aoff[6];
#pragma unroll
    for (int rr = 0; rr < 6; rr++) {
        int row = ty * 6 + rr;
        aoff[rr] = (row / U) * 48 + (row % U) * P;   // multiple of 4 floats
    }

    for (;;) {
        if (tid == 0) ibuf[31] = atomicAdd(&g_cursor[E], 1);
        __syncthreads();                 // orders prev compute vs next fill too
        int base = ibuf[31] * RPB2;
        if (base >= cnt) break;
        int nval = min(RPB2, cnt - base);
        if (tid < nval) ibuf[tid] = g_lists[E * NREG + base + tid];
        __syncthreads();

        for (int i = tid; i < nval * 12; i += 256) {
            int reg = i / 12, v = i - reg * 12;
            int rid = ibuf[reg];
            int n = rid / 7, r = rid - n * 7;
            ((float4*)xrs)[reg * 12 + v] = __ldg(&x4[n * 84 + r * 12 + v]);
        }
        __syncthreads();

#pragma unroll 1
        for (int h = 0; h < 2; h++) {    // two 12-row halves, NOT unrolled
            const int regbase = h * RH;
            if (regbase >= nval) break;  // block-uniform
            const float* xh = xrs + h * HOFF;

            float4 acc[6];
#pragma unroll
            for (int i = 0; i < 6; i++) acc[i] = make_float4(0.f, 0.f, 0.f, 0.f);

#pragma unroll
            for (int k = 0; k < P; k += 4) {
                float4 b0 = WSM ? ((const float4*)Wsm)[(k + 0) * 128 + tx]
                                : __ldg(&W4[(k + 0) * 128 + tx]);
                float4 b1 = WSM ? ((const float4*)Wsm)[(k + 1) * 128 + tx]
                                : __ldg(&W4[(k + 1) * 128 + tx]);
                float4 b2 = WSM ? ((const float4*)Wsm)[(k + 2) * 128 + tx]
                                : __ldg(&W4[(k + 2) * 128 + tx]);
                float4 b3 = WSM ? ((const float4*)Wsm)[(k + 3) * 128 + tx]
                                : __ldg(&W4[(k + 3) * 128 + tx]);
#pragma unroll
                for (int rr = 0; rr < 6; rr++) {
                    float4 a = *(const float4*)&xh[aoff[rr] + k]; // 1 LDS.128
                    acc[rr].x = fmaf(a.x, b0.x, acc[rr].x);
                    acc[rr].y = fmaf(a.x, b0.y, acc[rr].y);
                    acc[rr].z = fmaf(a.x, b0.z, acc[rr].z);
                    acc[rr].w = fmaf(a.x, b0.w, acc[rr].w);
                    acc[rr].x = fmaf(a.y, b1.x, acc[rr].x);
                    acc[rr].y = fmaf(a.y, b1.y, acc[rr].y);
                    acc[rr].z = fmaf(a.y, b1.z, acc[rr].z);
                    acc[rr].w = fmaf(a.y, b1.w, acc[rr].w);
                    acc[rr].x = fmaf(a.z, b2.x, acc[rr].x);
                    acc[rr].y = fmaf(a.z, b2.y, acc[rr].y);
                    acc[rr].z = fmaf(a.z, b2.z, acc[rr].z);
                    acc[rr].w = fmaf(a.z, b2.w, acc[rr].w);
                    acc[rr].x = fmaf(a.w, b3.x, acc[rr].x);
                    acc[rr].y = fmaf(a.w, b3.y, acc[rr].y);
                    acc[rr].z = fmaf(a.w, b3.z, acc[rr].z);
                    acc[rr].w = fmaf(a.w, b3.w, acc[rr].w);
                }
            }

            const float4* pe4 = (const float4*)g_pe;
#pragma unroll
            for (int rr = 0; rr < 6; rr++) {
                int row = ty * 6 + rr;
                int reg = regbase + row / U;
                int q   = row % U;
                if (reg >= nval) continue;
                int rid = ibuf[reg];
                int n = rid / 7, r = rid - n * 7;
#pragma unroll
                for (int t = q * K; t < ((q + 1) * K < 6 ? (q + 1) * K : 6); t++) {
                    int pos = r * 6 + t;
                    float4 p = __ldg(&pe4[pos * 128 + tx]);
                    float4 v = make_float4(acc[rr].x + p.x, acc[rr].y + p.y,
                                           acc[rr].z + p.z, acc[rr].w + p.w);
                    __stcs(&out4[(long long)n * 5376 + pos * 128 + tx], v);
                }
            }
        }
        // no end barrier: next iteration's post-atomic barrier orders reuse
    }
    __syncthreads();   // phase separation before Wsm/xrs/ibuf reuse
}

__global__ void __launch_bounds__(256, 4) embed_fused_kernel(
    const float4* __restrict__ x4,
    const float4* __restrict__ We0, const float4* __restrict__ We1,
    const float4* __restrict__ We2, const float4* __restrict__ We3,
    float4* __restrict__ out4)
{
    extern __shared__ float sm[];
    float* Wsm = sm;                       // up to 24*512 floats
    float* xrs = sm + 24 * 512;            // 24*48 floats (super-chunk)
    int*   ibuf = (int*)(xrs + 24 * 48);   // 32 ints

    embed_expert<48, false>(x4, We3, out4, Wsm, xrs, ibuf);
    embed_expert<24, true >(x4, We2, out4, Wsm, xrs, ibuf);
    embed_expert<16, true >(x4, We1, out4, Wsm, xrs, ibuf);
    embed_expert< 8, true >(x4, We0, out4, Wsm, xrs, ibuf);

    // last block out resets routing state for the next graph replay
    if (threadIdx.x == 0) {
        int d = atomicAdd(&g_done, 1);
        if (d == (int)gridDim.x - 1) {
            g_counts[0] = 0; g_counts[1] = 0; g_counts[2] = 0; g_counts[3] = 0;
            g_cursor[0] = 0; g_cursor[1] = 0; g_cursor[2] = 0; g_cursor[3] = 0;
            g_done = 0;
        }
    }
}

// --------------------------- launch ------------------------------------------
extern "C" void kernel_launch(void* const* d_in, const int* in_sizes, int n_in,
                              void* d_out, int out_size) {
    const float* x  = (const float*)d_in[0];
    const float* un = (const float*)d_in[1];
    const float* W1 = (const float*)d_in[2];
    const float* b1 = (const float*)d_in[3];
    const float* W2 = (const float*)d_in[4];
    const float* b2 = (const float*)d_in[5];
    const float4* We0 = (const float4*)d_in[6];
    const float4* We1 = (const float4*)d_in[7];
    const float4* We2 = (const float4*)d_in[8];
    const float4* We3 = (const float4*)d_in[9];
    float*  out  = (float*)d_out;
    float4* out4 = (float4*)d_out;
    const float4* x4 = (const float4*)d_in[0];

    int write_mode = 0;
    if ((long long)out_size >= XP_ELEMS + 1 + 28672) write_mode = 2;
    else if ((long long)out_size >= XP_ELEMS + 1)    write_mode = 1;

    const int SMEM = (24 * 512 + 24 * 48) * 4 + 128;   // 53888 bytes
    cudaFuncSetAttribute(embed_fused_kernel,
                         cudaFuncAttributeMaxDynamicSharedMemorySize, SMEM);

    router_kernel<<<448, 64>>>(x, un, W1, b1, W2, b2, out, write_mode);
    embed_fused_kernel<<<592, 256, SMEM>>>(x4, We0, We1, We2, We3, out4);
    (void)in_sizes; (void)n_in;
}